// round 2
// baseline (speedup 1.0000x reference)
#include <cuda_runtime.h>
#include <math.h>

#define TT 128
#define BB 32
#define EE 512
#define HH 512
#define UU 1024
#define VV 10000
#define G4 2048   // 4*H

// ---------------- scratch (static device globals; no allocation) ----------------
__device__ __align__(128) float g_X1 [TT*BB*G4];  // precomputed input gates, layer 1
__device__ __align__(128) float g_H1 [TT*BB*HH];  // all h1_t
__device__ __align__(128) float g_S  [TT*BB*UU];  // attention scores / weights
__device__ __align__(128) float g_CTX[TT*BB*HH];  // attention contexts
__device__ __align__(128) float g_X2 [TT*BB*G4];  // precomputed input gates, layer 2
__device__ __align__(128) float g_HS [TT*BB*HH];  // all h2_t
__device__ __align__(128) float g_c1 [BB*HH];
__device__ __align__(128) float g_c2 [BB*HH];

// ---------------- init cell states ----------------
__global__ void init_states(const float* __restrict__ c0,
                            float* __restrict__ c1, float* __restrict__ c2)
{
    int i = blockIdx.x * blockDim.x + threadIdx.x;
    if (i < BB * HH) {
        c1[i] = c0[i];
        c2[i] = c0[BB * HH + i];
    }
}

// ---------------- SGEMM  C = A(MxK) * B(NxK)^T + bias1 + bias2 ----------------
// 64x64 tile, BK=16, 256 threads, 4x4 register tile. Batched via blockIdx.z.
__global__ __launch_bounds__(256)
void sgemm_tn(const float* __restrict__ A, const float* __restrict__ B,
              float* __restrict__ C,
              const float* __restrict__ bias1, const float* __restrict__ bias2,
              int M, int N, int K, int lda, int ldb, int ldc,
              long long aBS, long long bBS, long long cBS)
{
    __shared__ float As[16][64];
    __shared__ float Bs[16][64];

    const int tid = threadIdx.x;
    const int tx = tid & 15;        // 0..15 -> n
    const int ty = tid >> 4;        // 0..15 -> m
    const int m0 = blockIdx.y * 64;
    const int n0 = blockIdx.x * 64;

    const float* Ab = A + (long long)blockIdx.z * aBS;
    const float* Bb = B + (long long)blockIdx.z * bBS;
    float*       Cb = C + (long long)blockIdx.z * cBS;

    const int lr = tid >> 2;          // 0..63 row within tile
    const int lk = (tid & 3) << 2;    // 0,4,8,12 k offset

    float acc[4][4];
    #pragma unroll
    for (int i = 0; i < 4; i++)
        #pragma unroll
        for (int j = 0; j < 4; j++) acc[i][j] = 0.f;

    for (int kt = 0; kt < K; kt += 16) {
        // A tile (transposed into As[k][m])
        {
            int m = m0 + lr;
            float4 v = make_float4(0.f, 0.f, 0.f, 0.f);
            if (m < M) v = *(const float4*)(Ab + (size_t)m * lda + kt + lk);
            As[lk + 0][lr] = v.x; As[lk + 1][lr] = v.y;
            As[lk + 2][lr] = v.z; As[lk + 3][lr] = v.w;
        }
        // B tile (transposed into Bs[k][n])
        {
            int n = n0 + lr;
            float4 v = make_float4(0.f, 0.f, 0.f, 0.f);
            if (n < N) v = *(const float4*)(Bb + (size_t)n * ldb + kt + lk);
            Bs[lk + 0][lr] = v.x; Bs[lk + 1][lr] = v.y;
            Bs[lk + 2][lr] = v.z; Bs[lk + 3][lr] = v.w;
        }
        __syncthreads();
        #pragma unroll
        for (int k = 0; k < 16; k++) {
            float a[4], b[4];
            *(float4*)a = *(const float4*)&As[k][ty << 2];
            *(float4*)b = *(const float4*)&Bs[k][tx << 2];
            #pragma unroll
            for (int i = 0; i < 4; i++)
                #pragma unroll
                for (int j = 0; j < 4; j++)
                    acc[i][j] += a[i] * b[j];
        }
        __syncthreads();
    }

    #pragma unroll
    for (int i = 0; i < 4; i++) {
        int m = m0 + (ty << 2) + i;
        if (m >= M) continue;
        #pragma unroll
        for (int j = 0; j < 4; j++) {
            int n = n0 + (tx << 2) + j;
            if (n < N) {
                float v = acc[i][j];
                if (bias1) v += bias1[n];
                if (bias2) v += bias2[n];
                Cb[(size_t)m * ldc + n] = v;
            }
        }
    }
}

// ---------------- SGEMM  C = A(MxK) * B(KxN) ----------------
__global__ __launch_bounds__(256)
void sgemm_nn(const float* __restrict__ A, const float* __restrict__ B,
              float* __restrict__ C,
              int M, int N, int K, int lda, int ldb, int ldc,
              long long aBS, long long bBS, long long cBS)
{
    __shared__ float As[16][64];
    __shared__ float Bs[16][64];

    const int tid = threadIdx.x;
    const int tx = tid & 15;
    const int ty = tid >> 4;
    const int m0 = blockIdx.y * 64;
    const int n0 = blockIdx.x * 64;

    const float* Ab = A + (long long)blockIdx.z * aBS;
    const float* Bb = B + (long long)blockIdx.z * bBS;
    float*       Cb = C + (long long)blockIdx.z * cBS;

    const int lr = tid >> 2;
    const int lk = (tid & 3) << 2;
    const int bkr = tid >> 4;          // 0..15 k row for B load
    const int bnc = (tid & 15) << 2;   // n offset for B load

    float acc[4][4];
    #pragma unroll
    for (int i = 0; i < 4; i++)
        #pragma unroll
        for (int j = 0; j < 4; j++) acc[i][j] = 0.f;

    for (int kt = 0; kt < K; kt += 16) {
        {
            int m = m0 + lr;
            float4 v = make_float4(0.f, 0.f, 0.f, 0.f);
            if (m < M) v = *(const float4*)(Ab + (size_t)m * lda + kt + lk);
            As[lk + 0][lr] = v.x; As[lk + 1][lr] = v.y;
            As[lk + 2][lr] = v.z; As[lk + 3][lr] = v.w;
        }
        {
            int n = n0 + bnc;
            float4 v = make_float4(0.f, 0.f, 0.f, 0.f);
            if (n < N) v = *(const float4*)(Bb + (size_t)(kt + bkr) * ldb + n);
            *(float4*)&Bs[bkr][bnc] = v;
        }
        __syncthreads();
        #pragma unroll
        for (int k = 0; k < 16; k++) {
            float a[4], b[4];
            *(float4*)a = *(const float4*)&As[k][ty << 2];
            *(float4*)b = *(const float4*)&Bs[k][tx << 2];
            #pragma unroll
            for (int i = 0; i < 4; i++)
                #pragma unroll
                for (int j = 0; j < 4; j++)
                    acc[i][j] += a[i] * b[j];
        }
        __syncthreads();
    }

    #pragma unroll
    for (int i = 0; i < 4; i++) {
        int m = m0 + (ty << 2) + i;
        if (m >= M) continue;
        #pragma unroll
        for (int j = 0; j < 4; j++) {
            int n = n0 + (tx << 2) + j;
            if (n < N) Cb[(size_t)m * ldc + n] = acc[i][j];
        }
    }
}

// ---------------- LSTM step: gates = Xpre + h_in @ Whh^T, then pointwise -------
// One warp per output (b,h): lanes split K, warp-reduce 4 gate dots.
__device__ __forceinline__ float sigmoidf_(float x) { return 1.f / (1.f + expf(-x)); }

__global__ __launch_bounds__(256)
void lstm_step(const float* __restrict__ Xpre,  // BB x G4 (this timestep)
               const float* __restrict__ Whh,   // G4 x HH
               const float* __restrict__ h_in,  // BB x HH (previous h)
               float* __restrict__ c_st,        // BB x HH (in-place)
               float* __restrict__ h_out)       // BB x HH (this timestep)
{
    const int gw   = (blockIdx.x * blockDim.x + threadIdx.x) >> 5;  // 0..16383
    const int lane = threadIdx.x & 31;
    const int b = gw >> 9;       // 0..31
    const int h = gw & 511;      // 0..511

    const float4* hv = (const float4*)h_in + b * 128 + lane * 4;   // 16 floats per lane
    const float4* W4 = (const float4*)Whh;
    const int col = lane * 4;

    float a0 = 0.f, a1 = 0.f, a2 = 0.f, a3 = 0.f;
    #pragma unroll
    for (int q = 0; q < 4; q++) {
        float4 x = hv[q];
        float4 w;
        w = W4[(size_t)(h)          * 128 + col + q];
        a0 += x.x * w.x + x.y * w.y + x.z * w.z + x.w * w.w;
        w = W4[(size_t)(512  + h)   * 128 + col + q];
        a1 += x.x * w.x + x.y * w.y + x.z * w.z + x.w * w.w;
        w = W4[(size_t)(1024 + h)   * 128 + col + q];
        a2 += x.x * w.x + x.y * w.y + x.z * w.z + x.w * w.w;
        w = W4[(size_t)(1536 + h)   * 128 + col + q];
        a3 += x.x * w.x + x.y * w.y + x.z * w.z + x.w * w.w;
    }
    #pragma unroll
    for (int off = 16; off > 0; off >>= 1) {
        a0 += __shfl_xor_sync(0xffffffffu, a0, off);
        a1 += __shfl_xor_sync(0xffffffffu, a1, off);
        a2 += __shfl_xor_sync(0xffffffffu, a2, off);
        a3 += __shfl_xor_sync(0xffffffffu, a3, off);
    }
    if (lane == 0) {
        const int base = b * G4;
        float gi = a0 + Xpre[base + h];
        float gf = a1 + Xpre[base + 512  + h];
        float gg = a2 + Xpre[base + 1024 + h];
        float go = a3 + Xpre[base + 1536 + h];
        gi = sigmoidf_(gi);
        gf = sigmoidf_(gf);
        gg = tanhf(gg);
        go = sigmoidf_(go);
        const int idx = b * HH + h;
        float c = gf * c_st[idx] + gi * gg;
        c_st[idx] = c;
        h_out[idx] = go * tanhf(c);
    }
}

// ---------------- row softmax (in place) ----------------
__global__ __launch_bounds__(256)
void softmax_rows(float* __restrict__ data, int L)
{
    float* p = data + (size_t)blockIdx.x * L;
    __shared__ float red[256];
    const int tid = threadIdx.x;

    float m = -3.4e38f;
    for (int i = tid; i < L; i += 256) m = fmaxf(m, p[i]);
    red[tid] = m; __syncthreads();
    #pragma unroll
    for (int s = 128; s > 0; s >>= 1) {
        if (tid < s) red[tid] = fmaxf(red[tid], red[tid + s]);
        __syncthreads();
    }
    m = red[0]; __syncthreads();

    float sum = 0.f;
    for (int i = tid; i < L; i += 256) {
        float e = expf(p[i] - m);
        p[i] = e;
        sum += e;
    }
    red[tid] = sum; __syncthreads();
    #pragma unroll
    for (int s = 128; s > 0; s >>= 1) {
        if (tid < s) red[tid] += red[tid + s];
        __syncthreads();
    }
    const float inv = 1.f / red[0];
    for (int i = tid; i < L; i += 256) p[i] *= inv;
}

// ---------------- launch ----------------
extern "C" void kernel_launch(void* const* d_in, const int* in_sizes, int n_in,
                              void* d_out, int out_size)
{
    const float* inputs = (const float*)d_in[0];
    const float* h0     = (const float*)d_in[1];
    const float* c0     = (const float*)d_in[2];
    const float* Lst    = (const float*)d_in[3];
    const float* W_ih1  = (const float*)d_in[4];
    const float* W_hh1  = (const float*)d_in[5];
    const float* b_ih1  = (const float*)d_in[6];
    const float* b_hh1  = (const float*)d_in[7];
    const float* W_ih2  = (const float*)d_in[8];
    const float* W_hh2  = (const float*)d_in[9];
    const float* b_ih2  = (const float*)d_in[10];
    const float* b_hh2  = (const float*)d_in[11];
    const float* W_out  = (const float*)d_in[12];
    const float* b_out  = (const float*)d_in[13];
    float* out = (float*)d_out;

    void* p;
    cudaGetSymbolAddress(&p, g_X1);  float* X1  = (float*)p;
    cudaGetSymbolAddress(&p, g_H1);  float* H1  = (float*)p;
    cudaGetSymbolAddress(&p, g_S);   float* S   = (float*)p;
    cudaGetSymbolAddress(&p, g_CTX); float* CTX = (float*)p;
    cudaGetSymbolAddress(&p, g_X2);  float* X2  = (float*)p;
    cudaGetSymbolAddress(&p, g_HS);  float* HS  = (float*)p;
    cudaGetSymbolAddress(&p, g_c1);  float* c1  = (float*)p;
    cudaGetSymbolAddress(&p, g_c2);  float* c2  = (float*)p;

    init_states<<<64, 256>>>(c0, c1, c2);

    // X1 = inputs @ W_ih1^T + b_ih1 + b_hh1   (4096 x 2048, K=512)
    {
        dim3 g(G4 / 64, (TT * BB) / 64, 1);
        sgemm_tn<<<g, 256>>>(inputs, W_ih1, X1, b_ih1, b_hh1,
                             TT * BB, G4, EE, EE, EE, G4, 0, 0, 0);
    }

    // layer-1 recurrence
    for (int t = 0; t < TT; t++) {
        const float* hin = (t == 0) ? h0 : (H1 + (size_t)(t - 1) * BB * HH);
        lstm_step<<<2048, 256>>>(X1 + (size_t)t * BB * G4, W_hh1, hin, c1,
                                 H1 + (size_t)t * BB * HH);
    }

    // attention: S[t,b,u] = sum_h H1[t,b,h] * L[u,b,h]   (batched over b)
    {
        dim3 g(UU / 64, TT / 64, BB);
        sgemm_tn<<<g, 256>>>(H1, Lst, S, nullptr, nullptr,
                             TT, UU, HH, BB * HH, BB * HH, BB * UU,
                             HH, HH, UU);
    }
    softmax_rows<<<TT * BB, 256>>>(S, UU);
    // CTX[t,b,h] = sum_u S[t,b,u] * L[u,b,h]
    {
        dim3 g(HH / 64, TT / 64, BB);
        sgemm_nn<<<g, 256>>>(S, Lst, CTX,
                             TT, HH, UU, BB * UU, BB * HH, BB * HH,
                             UU, HH, HH);
    }

    // X2 = CTX @ W_ih2^T + b_ih2 + b_hh2
    {
        dim3 g(G4 / 64, (TT * BB) / 64, 1);
        sgemm_tn<<<g, 256>>>(CTX, W_ih2, X2, b_ih2, b_hh2,
                             TT * BB, G4, HH, HH, HH, G4, 0, 0, 0);
    }

    // layer-2 recurrence
    for (int t = 0; t < TT; t++) {
        const float* hin = (t == 0) ? (h0 + BB * HH) : (HS + (size_t)(t - 1) * BB * HH);
        lstm_step<<<2048, 256>>>(X2 + (size_t)t * BB * G4, W_hh2, hin, c2,
                                 HS + (size_t)t * BB * HH);
    }

    // logits = HS @ W_out^T + b_out  -> d_out, then softmax over V
    {
        dim3 g((VV + 63) / 64, (TT * BB) / 64, 1);
        sgemm_tn<<<g, 256>>>(HS, W_out, out, b_out, nullptr,
                             TT * BB, VV, HH, HH, HH, VV, 0, 0, 0);
    }
    softmax_rows<<<TT * BB, 256>>>(out, VV);
}

// round 3
// speedup vs baseline: 1.9181x; 1.9181x over previous
#include <cuda_runtime.h>
#include <math.h>

#define TT 128
#define BB 32
#define EE 512
#define HH 512
#define UU 1024
#define VV 10000
#define G4 2048   // 4*H

#define NBLK 128          // persistent kernel blocks (<=148 SMs -> co-resident)
#define NTILES 16         // n tiles of 128 columns
#define KSPLIT 8          // k slices of 64

// ---------------- scratch (static device globals; no allocation) ----------------
__device__ __align__(128) float g_X1 [TT*BB*G4];
__device__ __align__(128) float g_H1 [TT*BB*HH];
__device__ __align__(128) float g_S  [TT*BB*UU];
__device__ __align__(128) float g_CTX[TT*BB*HH];
__device__ __align__(128) float g_X2 [TT*BB*G4];
__device__ __align__(128) float g_HS [TT*BB*HH];
__device__ __align__(128) float g_c1 [BB*HH];
__device__ __align__(128) float g_c2 [BB*HH];
__device__ __align__(128) float g_P  [KSPLIT*G4*BB];   // k-split partials, 2MB

__device__ unsigned g_bar_arrive;
__device__ unsigned g_bar_epoch;

// ---------------- init cell states ----------------
__global__ void init_states(const float* __restrict__ c0,
                            float* __restrict__ c1, float* __restrict__ c2)
{
    int i = blockIdx.x * blockDim.x + threadIdx.x;
    if (i < BB * HH) {
        c1[i] = c0[i];
        c2[i] = c0[BB * HH + i];
    }
}

__global__ void bar_reset()
{
    g_bar_arrive = 0;
    g_bar_epoch  = 0;
}

// ---------------- software grid barrier (all NBLK blocks co-resident) ----------
__device__ __forceinline__ void grid_barrier(unsigned target)
{
    __syncthreads();
    if (threadIdx.x == 0) {
        __threadfence();
        unsigned prev = atomicAdd(&g_bar_arrive, 1u);
        if (prev == NBLK - 1) {
            g_bar_arrive = 0;
            __threadfence();
            atomicExch(&g_bar_epoch, target);
        } else {
            while (*(volatile unsigned*)&g_bar_epoch < target) { }
        }
        __threadfence();
    }
    __syncthreads();
}

__device__ __forceinline__ float sigmoidf_(float x) { return 1.f / (1.f + expf(-x)); }

// ---------------- persistent LSTM recurrence -----------------------------------
// gates[t] = Xpre[t] + h_{t-1} @ Whh^T ; pointwise LSTM ; h_t -> Hout[t]
// Block (ntile, ks): ntile covers 128 gate-columns, ks covers 64 k.
// Thread: 4n x 4b register tile. W tile staged in smem ONCE for all 128 steps.
__global__ __launch_bounds__(256)
void lstm_seq(const float* __restrict__ Xpre,   // [T][B][G4]
              const float* __restrict__ Whh,    // [G4][H]
              const float* __restrict__ h0row,  // [B][H]
              float* __restrict__ c,            // [B][H]
              float* __restrict__ Hout)         // [T][B][H]
{
    __shared__ float4 Wt[32 * 65 + 1];   // Wt[nq][kk] = W[n0+4nq+0..3][k0+kk], pad 65
    __shared__ float  hs[64 * 36];       // hs[kk][b], pad 36

    const int bid   = blockIdx.x;
    const int ntile = bid & (NTILES - 1);
    const int ks    = bid >> 4;
    const int n0    = ntile * 128;
    const int k0    = ks * 64;
    const int tid   = threadIdx.x;

    // stage W tile once (invariant across timesteps)
    for (int idx = tid; idx < 32 * 64; idx += 256) {
        int nq = idx >> 6, kk = idx & 63;
        int n  = n0 + nq * 4;
        Wt[nq * 65 + kk] = make_float4(
            Whh[(size_t)(n + 0) * HH + k0 + kk],
            Whh[(size_t)(n + 1) * HH + k0 + kk],
            Whh[(size_t)(n + 2) * HH + k0 + kk],
            Whh[(size_t)(n + 3) * HH + k0 + kk]);
    }

    const int bq = tid & 7;    // b-group: 4 b's, lanes cover all 8 groups
    const int nq = tid >> 3;   // n-group: 4 n's
    const int hb = tid >> 3;   // for h-slice load: b row
    const int hk = tid & 7;    // k sub-group

    float* Pbase = g_P + ((size_t)(ks * G4 + n0 + nq * 4) * BB) + bq * 4;

    __syncthreads();

    unsigned ep = 0;
    for (int t = 0; t < TT; t++) {
        const float* hprev = (t == 0) ? h0row : (Hout + (size_t)(t - 1) * BB * HH);

        // load h slice -> hs[kk][b] (transposed, padded)
        #pragma unroll
        for (int r = 0; r < 2; r++) {
            int kg = hk + r * 8;                     // 0..15, kk = 4*kg
            float4 v = *(const float4*)(hprev + (size_t)hb * HH + k0 + kg * 4);
            int kk = kg * 4;
            hs[(kk + 0) * 36 + hb] = v.x;
            hs[(kk + 1) * 36 + hb] = v.y;
            hs[(kk + 2) * 36 + hb] = v.z;
            hs[(kk + 3) * 36 + hb] = v.w;
        }
        __syncthreads();

        // 4n x 4b x 64k
        float acc[4][4];
        #pragma unroll
        for (int i = 0; i < 4; i++)
            #pragma unroll
            for (int j = 0; j < 4; j++) acc[i][j] = 0.f;

        #pragma unroll 4
        for (int kk = 0; kk < 64; kk += 4) {
            float4 w0 = Wt[nq * 65 + kk + 0];
            float4 w1 = Wt[nq * 65 + kk + 1];
            float4 w2 = Wt[nq * 65 + kk + 2];
            float4 w3 = Wt[nq * 65 + kk + 3];
            float4 h0v = *(const float4*)&hs[(kk + 0) * 36 + bq * 4];
            float4 h1v = *(const float4*)&hs[(kk + 1) * 36 + bq * 4];
            float4 h2v = *(const float4*)&hs[(kk + 2) * 36 + bq * 4];
            float4 h3v = *(const float4*)&hs[(kk + 3) * 36 + bq * 4];

            acc[0][0] += w0.x*h0v.x + w1.x*h1v.x + w2.x*h2v.x + w3.x*h3v.x;
            acc[0][1] += w0.x*h0v.y + w1.x*h1v.y + w2.x*h2v.y + w3.x*h3v.y;
            acc[0][2] += w0.x*h0v.z + w1.x*h1v.z + w2.x*h2v.z + w3.x*h3v.z;
            acc[0][3] += w0.x*h0v.w + w1.x*h1v.w + w2.x*h2v.w + w3.x*h3v.w;
            acc[1][0] += w0.y*h0v.x + w1.y*h1v.x + w2.y*h2v.x + w3.y*h3v.x;
            acc[1][1] += w0.y*h0v.y + w1.y*h1v.y + w2.y*h2v.y + w3.y*h3v.y;
            acc[1][2] += w0.y*h0v.z + w1.y*h1v.z + w2.y*h2v.z + w3.y*h3v.z;
            acc[1][3] += w0.y*h0v.w + w1.y*h1v.w + w2.y*h2v.w + w3.y*h3v.w;
            acc[2][0] += w0.z*h0v.x + w1.z*h1v.x + w2.z*h2v.x + w3.z*h3v.x;
            acc[2][1] += w0.z*h0v.y + w1.z*h1v.y + w2.z*h2v.y + w3.z*h3v.y;
            acc[2][2] += w0.z*h0v.z + w1.z*h1v.z + w2.z*h2v.z + w3.z*h3v.z;
            acc[2][3] += w0.z*h0v.w + w1.z*h1v.w + w2.z*h2v.w + w3.z*h3v.w;
            acc[3][0] += w0.w*h0v.x + w1.w*h1v.x + w2.w*h2v.x + w3.w*h3v.x;
            acc[3][1] += w0.w*h0v.y + w1.w*h1v.y + w2.w*h2v.y + w3.w*h3v.y;
            acc[3][2] += w0.w*h0v.z + w1.w*h1v.z + w2.w*h2v.z + w3.w*h3v.z;
            acc[3][3] += w0.w*h0v.w + w1.w*h1v.w + w2.w*h2v.w + w3.w*h3v.w;
        }

        // write partials P[ks][n][b]
        #pragma unroll
        for (int i = 0; i < 4; i++) {
            float4 v = make_float4(acc[i][0], acc[i][1], acc[i][2], acc[i][3]);
            *(float4*)(Pbase + (size_t)i * BB) = v;
        }

        grid_barrier(++ep);

        // reduce + pointwise: 16384 cells over blocks 0..63
        if (bid < 64) {
            int cell = bid * 256 + tid;
            int b = cell & 31;
            int h = cell >> 5;
            const float* xp = Xpre + (size_t)t * BB * G4 + (size_t)b * G4;
            float gi = xp[h];
            float gf = xp[512 + h];
            float gg = xp[1024 + h];
            float go = xp[1536 + h];
            #pragma unroll
            for (int s = 0; s < KSPLIT; s++) {
                const float* pp = g_P + (size_t)s * G4 * BB;
                gi += __ldcg(pp + (size_t)(h)        * BB + b);
                gf += __ldcg(pp + (size_t)(512  + h) * BB + b);
                gg += __ldcg(pp + (size_t)(1024 + h) * BB + b);
                go += __ldcg(pp + (size_t)(1536 + h) * BB + b);
            }
            gi = sigmoidf_(gi);
            gf = sigmoidf_(gf);
            gg = tanhf(gg);
            go = sigmoidf_(go);
            int idx = b * HH + h;
            float cv = gf * c[idx] + gi * gg;
            c[idx] = cv;
            Hout[(size_t)t * BB * HH + idx] = go * tanhf(cv);
        }

        grid_barrier(++ep);
    }
}

// ---------------- SGEMM  C = A(MxK) * B(NxK)^T + bias1 + bias2 ----------------
__global__ __launch_bounds__(256)
void sgemm_tn(const float* __restrict__ A, const float* __restrict__ B,
              float* __restrict__ C,
              const float* __restrict__ bias1, const float* __restrict__ bias2,
              int M, int N, int K, int lda, int ldb, int ldc,
              long long aBS, long long bBS, long long cBS)
{
    __shared__ float As[16][64];
    __shared__ float Bs[16][64];

    const int tid = threadIdx.x;
    const int tx = tid & 15;
    const int ty = tid >> 4;
    const int m0 = blockIdx.y * 64;
    const int n0 = blockIdx.x * 64;

    const float* Ab = A + (long long)blockIdx.z * aBS;
    const float* Bb = B + (long long)blockIdx.z * bBS;
    float*       Cb = C + (long long)blockIdx.z * cBS;

    const int lr = tid >> 2;
    const int lk = (tid & 3) << 2;

    float acc[4][4];
    #pragma unroll
    for (int i = 0; i < 4; i++)
        #pragma unroll
        for (int j = 0; j < 4; j++) acc[i][j] = 0.f;

    for (int kt = 0; kt < K; kt += 16) {
        {
            int m = m0 + lr;
            float4 v = make_float4(0.f, 0.f, 0.f, 0.f);
            if (m < M) v = *(const float4*)(Ab + (size_t)m * lda + kt + lk);
            As[lk + 0][lr] = v.x; As[lk + 1][lr] = v.y;
            As[lk + 2][lr] = v.z; As[lk + 3][lr] = v.w;
        }
        {
            int n = n0 + lr;
            float4 v = make_float4(0.f, 0.f, 0.f, 0.f);
            if (n < N) v = *(const float4*)(Bb + (size_t)n * ldb + kt + lk);
            Bs[lk + 0][lr] = v.x; Bs[lk + 1][lr] = v.y;
            Bs[lk + 2][lr] = v.z; Bs[lk + 3][lr] = v.w;
        }
        __syncthreads();
        #pragma unroll
        for (int k = 0; k < 16; k++) {
            float a[4], b[4];
            *(float4*)a = *(const float4*)&As[k][ty << 2];
            *(float4*)b = *(const float4*)&Bs[k][tx << 2];
            #pragma unroll
            for (int i = 0; i < 4; i++)
                #pragma unroll
                for (int j = 0; j < 4; j++)
                    acc[i][j] += a[i] * b[j];
        }
        __syncthreads();
    }

    #pragma unroll
    for (int i = 0; i < 4; i++) {
        int m = m0 + (ty << 2) + i;
        if (m >= M) continue;
        #pragma unroll
        for (int j = 0; j < 4; j++) {
            int n = n0 + (tx << 2) + j;
            if (n < N) {
                float v = acc[i][j];
                if (bias1) v += bias1[n];
                if (bias2) v += bias2[n];
                Cb[(size_t)m * ldc + n] = v;
            }
        }
    }
}

// ---------------- SGEMM  C = A(MxK) * B(KxN) ----------------
__global__ __launch_bounds__(256)
void sgemm_nn(const float* __restrict__ A, const float* __restrict__ B,
              float* __restrict__ C,
              int M, int N, int K, int lda, int ldb, int ldc,
              long long aBS, long long bBS, long long cBS)
{
    __shared__ float As[16][64];
    __shared__ float Bs[16][64];

    const int tid = threadIdx.x;
    const int tx = tid & 15;
    const int ty = tid >> 4;
    const int m0 = blockIdx.y * 64;
    const int n0 = blockIdx.x * 64;

    const float* Ab = A + (long long)blockIdx.z * aBS;
    const float* Bb = B + (long long)blockIdx.z * bBS;
    float*       Cb = C + (long long)blockIdx.z * cBS;

    const int lr = tid >> 2;
    const int lk = (tid & 3) << 2;
    const int bkr = tid >> 4;
    const int bnc = (tid & 15) << 2;

    float acc[4][4];
    #pragma unroll
    for (int i = 0; i < 4; i++)
        #pragma unroll
        for (int j = 0; j < 4; j++) acc[i][j] = 0.f;

    for (int kt = 0; kt < K; kt += 16) {
        {
            int m = m0 + lr;
            float4 v = make_float4(0.f, 0.f, 0.f, 0.f);
            if (m < M) v = *(const float4*)(Ab + (size_t)m * lda + kt + lk);
            As[lk + 0][lr] = v.x; As[lk + 1][lr] = v.y;
            As[lk + 2][lr] = v.z; As[lk + 3][lr] = v.w;
        }
        {
            int n = n0 + bnc;
            float4 v = make_float4(0.f, 0.f, 0.f, 0.f);
            if (n < N) v = *(const float4*)(Bb + (size_t)(kt + bkr) * ldb + n);
            *(float4*)&Bs[bkr][bnc] = v;
        }
        __syncthreads();
        #pragma unroll
        for (int k = 0; k < 16; k++) {
            float a[4], b[4];
            *(float4*)a = *(const float4*)&As[k][ty << 2];
            *(float4*)b = *(const float4*)&Bs[k][tx << 2];
            #pragma unroll
            for (int i = 0; i < 4; i++)
                #pragma unroll
                for (int j = 0; j < 4; j++)
                    acc[i][j] += a[i] * b[j];
        }
        __syncthreads();
    }

    #pragma unroll
    for (int i = 0; i < 4; i++) {
        int m = m0 + (ty << 2) + i;
        if (m >= M) continue;
        #pragma unroll
        for (int j = 0; j < 4; j++) {
            int n = n0 + (tx << 2) + j;
            if (n < N) Cb[(size_t)m * ldc + n] = acc[i][j];
        }
    }
}

// ---------------- row softmax (in place) ----------------
__global__ __launch_bounds__(256)
void softmax_rows(float* __restrict__ data, int L)
{
    float* p = data + (size_t)blockIdx.x * L;
    __shared__ float red[256];
    const int tid = threadIdx.x;

    float m = -3.4e38f;
    for (int i = tid; i < L; i += 256) m = fmaxf(m, p[i]);
    red[tid] = m; __syncthreads();
    #pragma unroll
    for (int s = 128; s > 0; s >>= 1) {
        if (tid < s) red[tid] = fmaxf(red[tid], red[tid + s]);
        __syncthreads();
    }
    m = red[0]; __syncthreads();

    float sum = 0.f;
    for (int i = tid; i < L; i += 256) {
        float e = expf(p[i] - m);
        p[i] = e;
        sum += e;
    }
    red[tid] = sum; __syncthreads();
    #pragma unroll
    for (int s = 128; s > 0; s >>= 1) {
        if (tid < s) red[tid] += red[tid + s];
        __syncthreads();
    }
    const float inv = 1.f / red[0];
    for (int i = tid; i < L; i += 256) p[i] *= inv;
}

// ---------------- launch ----------------
extern "C" void kernel_launch(void* const* d_in, const int* in_sizes, int n_in,
                              void* d_out, int out_size)
{
    const float* inputs = (const float*)d_in[0];
    const float* h0     = (const float*)d_in[1];
    const float* c0     = (const float*)d_in[2];
    const float* Lst    = (const float*)d_in[3];
    const float* W_ih1  = (const float*)d_in[4];
    const float* W_hh1  = (const float*)d_in[5];
    const float* b_ih1  = (const float*)d_in[6];
    const float* b_hh1  = (const float*)d_in[7];
    const float* W_ih2  = (const float*)d_in[8];
    const float* W_hh2  = (const float*)d_in[9];
    const float* b_ih2  = (const float*)d_in[10];
    const float* b_hh2  = (const float*)d_in[11];
    const float* W_out  = (const float*)d_in[12];
    const float* b_out  = (const float*)d_in[13];
    float* out = (float*)d_out;

    void* p;
    cudaGetSymbolAddress(&p, g_X1);  float* X1  = (float*)p;
    cudaGetSymbolAddress(&p, g_H1);  float* H1  = (float*)p;
    cudaGetSymbolAddress(&p, g_S);   float* S   = (float*)p;
    cudaGetSymbolAddress(&p, g_CTX); float* CTX = (float*)p;
    cudaGetSymbolAddress(&p, g_X2);  float* X2  = (float*)p;
    cudaGetSymbolAddress(&p, g_HS);  float* HS  = (float*)p;
    cudaGetSymbolAddress(&p, g_c1);  float* c1  = (float*)p;
    cudaGetSymbolAddress(&p, g_c2);  float* c2  = (float*)p;

    init_states<<<64, 256>>>(c0, c1, c2);

    // X1 = inputs @ W_ih1^T + b_ih1 + b_hh1
    {
        dim3 g(G4 / 64, (TT * BB) / 64, 1);
        sgemm_tn<<<g, 256>>>(inputs, W_ih1, X1, b_ih1, b_hh1,
                             TT * BB, G4, EE, EE, EE, G4, 0, 0, 0);
    }

    // layer-1 recurrence (persistent)
    bar_reset<<<1, 1>>>();
    lstm_seq<<<NBLK, 256>>>(X1, W_hh1, h0, c1, H1);

    // attention: S[t,b,u] = sum_h H1[t,b,h] * L[u,b,h]
    {
        dim3 g(UU / 64, TT / 64, BB);
        sgemm_tn<<<g, 256>>>(H1, Lst, S, nullptr, nullptr,
                             TT, UU, HH, BB * HH, BB * HH, BB * UU,
                             HH, HH, UU);
    }
    softmax_rows<<<TT * BB, 256>>>(S, UU);
    // CTX[t,b,h] = sum_u S[t,b,u] * L[u,b,h]
    {
        dim3 g(HH / 64, TT / 64, BB);
        sgemm_nn<<<g, 256>>>(S, Lst, CTX,
                             TT, HH, UU, BB * UU, BB * HH, BB * HH,
                             UU, HH, HH);
    }

    // X2 = CTX @ W_ih2^T + b_ih2 + b_hh2
    {
        dim3 g(G4 / 64, (TT * BB) / 64, 1);
        sgemm_tn<<<g, 256>>>(CTX, W_ih2, X2, b_ih2, b_hh2,
                             TT * BB, G4, HH, HH, HH, G4, 0, 0, 0);
    }

    // layer-2 recurrence (persistent)
    bar_reset<<<1, 1>>>();
    lstm_seq<<<NBLK, 256>>>(X2, W_hh2, h0 + BB * HH, c2, HS);

    // logits = HS @ W_out^T + b_out -> softmax over V
    {
        dim3 g((VV + 63) / 64, (TT * BB) / 64, 1);
        sgemm_tn<<<g, 256>>>(HS, W_out, out, b_out, nullptr,
                             TT * BB, VV, HH, HH, HH, VV, 0, 0, 0);
    }
    softmax_rows<<<TT * BB, 256>>>(out, VV);
}